// round 1
// baseline (speedup 1.0000x reference)
#include <cuda_runtime.h>
#include <cuda_bf16.h>
#include <cstdint>

#define EPS 1e-5f

static constexpr int MAX_N = 50048;    // nodes (actual 50000)
static constexpr int MAX_E = 600064;   // edges (actual 600000)

// ---------------- scratch (device globals; no allocation allowed) ------------
__device__ float  g_deg[MAX_N];
__device__ float  g_dinv[MAX_N];
__device__ float  g_normself[MAX_N];
__device__ float  g_norm[MAX_E];
__device__ float4 g_h2[MAX_N * 32];    // up to 128 floats/node (GEMM output)
__device__ float4 g_out[MAX_N * 32];   // aggregation output
__device__ float4 g_h[MAX_N * 32];     // activations between layers
__device__ float  g_stats[256];        // [0..128) sum, [128..256) sumsq
__device__ __align__(16) float g_scale[128];
__device__ __align__(16) float g_shift[128];

// ---------------- small prep kernels ----------------------------------------
__global__ void k_deg_init(float* deg, int n) {
    int i = blockIdx.x * blockDim.x + threadIdx.x;
    if (i < n) deg[i] = 1.0f;   // self loop weight
}

__global__ void k_deg_acc(const int* __restrict__ dst, const float* __restrict__ w,
                          float* deg, int e) {
    int i = blockIdx.x * blockDim.x + threadIdx.x;
    if (i < e) atomicAdd(deg + dst[i], w[i]);
}

__global__ void k_dinv(const float* __restrict__ deg, float* dinv, float* normself, int n) {
    int i = blockIdx.x * blockDim.x + threadIdx.x;
    if (i < n) {
        float d = deg[i];
        float r = (d > 0.0f) ? rsqrtf(d) : 0.0f;
        dinv[i] = r;
        normself[i] = r * r;
    }
}

__global__ void k_norm(const int* __restrict__ src, const int* __restrict__ dst,
                       const float* __restrict__ w, const float* __restrict__ dinv,
                       float* norm, int e) {
    int i = blockIdx.x * blockDim.x + threadIdx.x;
    if (i < e) norm[i] = dinv[src[i]] * w[i] * dinv[dst[i]];
}

__global__ void k_zero_stats() {
    int i = threadIdx.x;
    if (i < 256) g_stats[i] = 0.0f;
}

// ---------------- tiled fp32 GEMM: C[M,NOUT] = A[M,K] @ B[K,NOUT] ------------
template <int K, int NOUT>
__global__ void k_gemm(const float* __restrict__ A, const float* __restrict__ B,
                       float* __restrict__ C, int M) {
    constexpr int BM = 64, BK = 32, TN = 4;
    constexpr int TM = (BM * NOUT) / (256 * TN);   // 8 / 4 / 2
    __shared__ float  As[BK][BM + 1];
    __shared__ float4 Bs[BK][NOUT / 4];

    const int tid = threadIdx.x;
    const int tx = tid % (NOUT / TN);
    const int ty = tid / (NOUT / TN);
    const int rowBase = blockIdx.x * BM;

    float acc[TM][4];
#pragma unroll
    for (int i = 0; i < TM; i++) { acc[i][0] = 0.f; acc[i][1] = 0.f; acc[i][2] = 0.f; acc[i][3] = 0.f; }

    for (int kt = 0; kt < K; kt += BK) {
        // load A tile (BM x BK), store transposed
#pragma unroll
        for (int l = tid; l < BM * BK / 4; l += 256) {
            int r = l >> 3;           // row in tile (BK/4 == 8 float4 per row)
            int c4 = l & 7;
            float4 v = make_float4(0.f, 0.f, 0.f, 0.f);
            int gr = rowBase + r;
            if (gr < M) v = *reinterpret_cast<const float4*>(A + (size_t)gr * K + kt + c4 * 4);
            As[c4 * 4 + 0][r] = v.x;
            As[c4 * 4 + 1][r] = v.y;
            As[c4 * 4 + 2][r] = v.z;
            As[c4 * 4 + 3][r] = v.w;
        }
        // load B tile (BK x NOUT)
#pragma unroll
        for (int l = tid; l < BK * NOUT / 4; l += 256) {
            int r = l / (NOUT / 4);
            int c4 = l % (NOUT / 4);
            Bs[r][c4] = *reinterpret_cast<const float4*>(B + (size_t)(kt + r) * NOUT + c4 * 4);
        }
        __syncthreads();
#pragma unroll
        for (int k = 0; k < BK; k++) {
            float4 bv = Bs[k][tx];
#pragma unroll
            for (int i = 0; i < TM; i++) {
                float a = As[k][ty * TM + i];
                acc[i][0] += a * bv.x;
                acc[i][1] += a * bv.y;
                acc[i][2] += a * bv.z;
                acc[i][3] += a * bv.w;
            }
        }
        __syncthreads();
    }
#pragma unroll
    for (int i = 0; i < TM; i++) {
        int gr = rowBase + ty * TM + i;
        if (gr < M) {
            *reinterpret_cast<float4*>(C + (size_t)gr * NOUT + tx * 4) =
                make_float4(acc[i][0], acc[i][1], acc[i][2], acc[i][3]);
        }
    }
}

// ---------------- out = normself * h2 + bias (self-loop + bias) -------------
template <int FEAT>
__global__ void k_init_out(const float4* __restrict__ h2, const float* __restrict__ b,
                           const float* __restrict__ normself, float4* __restrict__ out,
                           int count4) {
    constexpr int F4 = FEAT / 4;
    int idx = blockIdx.x * blockDim.x + threadIdx.x;
    if (idx >= count4) return;
    int node = idx / F4;
    int f4 = idx % F4;
    float ns = normself[node];
    float4 v = h2[idx];
    float4 bb = *reinterpret_cast<const float4*>(b + f4 * 4);
    out[idx] = make_float4(fmaf(ns, v.x, bb.x), fmaf(ns, v.y, bb.y),
                           fmaf(ns, v.z, bb.z), fmaf(ns, v.w, bb.w));
}

// ---------------- edge scatter with vectorized reductions -------------------
template <int FEAT>
__global__ void k_scatter(const int* __restrict__ src, const int* __restrict__ dst,
                          const float* __restrict__ norm, const float* __restrict__ h2,
                          float* __restrict__ out, int E) {
    constexpr int LPE = FEAT / 4;      // lanes per edge
    constexpr int EPW = 32 / LPE;      // edges per warp
    int lane = threadIdx.x & 31;
    int warpGlobal = (blockIdx.x * blockDim.x + threadIdx.x) >> 5;
    int sub = lane / LPE;
    int fc = lane % LPE;
    int e = warpGlobal * EPW + sub;
    if (e >= E) return;
    int s = src[e];
    int d = dst[e];
    float n = norm[e];
    float4 v = *reinterpret_cast<const float4*>(h2 + (size_t)s * FEAT + fc * 4);
    float mx = v.x * n, my = v.y * n, mz = v.z * n, mw = v.w * n;
    float* p = out + (size_t)d * FEAT + fc * 4;
    asm volatile("red.global.add.v4.f32 [%0], {%1, %2, %3, %4};"
                 :: "l"(p), "f"(mx), "f"(my), "f"(mz), "f"(mw)
                 : "memory");
}

// ---------------- BatchNorm: stats, finalize, apply --------------------------
template <int FEAT>
__global__ void k_bn_stats(const float* __restrict__ h, int Nn) {
    constexpr int C = FEAT / 32;
    int lane = threadIdx.x & 31;
    int wid = threadIdx.x >> 5;
    int warpGlobal = (blockIdx.x * blockDim.x + threadIdx.x) >> 5;
    int nWarps = (gridDim.x * blockDim.x) >> 5;
    float s[C], q[C];
#pragma unroll
    for (int c = 0; c < C; c++) { s[c] = 0.f; q[c] = 0.f; }
    for (int r = warpGlobal; r < Nn; r += nWarps) {
        const float* p = h + (size_t)r * FEAT;
#pragma unroll
        for (int c = 0; c < C; c++) {
            float v = p[c * 32 + lane];
            s[c] += v;
            q[c] += v * v;
        }
    }
    __shared__ float sh_s[8][FEAT];
    __shared__ float sh_q[8][FEAT];
#pragma unroll
    for (int c = 0; c < C; c++) {
        sh_s[wid][c * 32 + lane] = s[c];
        sh_q[wid][c * 32 + lane] = q[c];
    }
    __syncthreads();
    int tid = threadIdx.x;
    if (tid < FEAT) {
        float a = 0.f, b = 0.f;
#pragma unroll
        for (int w = 0; w < 8; w++) { a += sh_s[w][tid]; b += sh_q[w][tid]; }
        atomicAdd(&g_stats[tid], a);
        atomicAdd(&g_stats[128 + tid], b);
    }
}

template <int FEAT>
__global__ void k_bn_finalize(const float* __restrict__ gamma, const float* __restrict__ beta,
                              float invN) {
    int f = threadIdx.x;
    if (f < FEAT) {
        float s = g_stats[f];
        float q = g_stats[128 + f];
        float mean = s * invN;
        float var = q * invN - mean * mean;
        float sc = gamma[f] * rsqrtf(var + EPS);
        g_scale[f] = sc;
        g_shift[f] = beta[f] - mean * sc;
    }
}

template <int FEAT>
__global__ void k_bn_apply(const float4* __restrict__ in, float4* __restrict__ out, int count4) {
    constexpr int F4 = FEAT / 4;
    int idx = blockIdx.x * blockDim.x + threadIdx.x;
    if (idx >= count4) return;
    int f4 = idx % F4;
    float4 v = in[idx];
    float4 sc = *reinterpret_cast<const float4*>(g_scale + f4 * 4);
    float4 sh = *reinterpret_cast<const float4*>(g_shift + f4 * 4);
    float rx = fmaf(v.x, sc.x, sh.x);
    float ry = fmaf(v.y, sc.y, sh.y);
    float rz = fmaf(v.z, sc.z, sh.z);
    float rw = fmaf(v.w, sc.w, sh.w);
    out[idx] = make_float4(fmaxf(rx, 0.f), fmaxf(ry, 0.f), fmaxf(rz, 0.f), fmaxf(rw, 0.f));
}

// ---------------- host orchestration -----------------------------------------
static inline int cdiv(int a, int b) { return (a + b - 1) / b; }

extern "C" void kernel_launch(void* const* d_in, const int* in_sizes, int n_in,
                              void* d_out, int out_size) {
    const float* x      = (const float*)d_in[0];
    const int*   src    = (const int*)d_in[1];
    const int*   dst    = (const int*)d_in[2];
    const float* weight = (const float*)d_in[3];
    const float* W1 = (const float*)d_in[4];
    const float* b1 = (const float*)d_in[5];
    const float* ga1 = (const float*)d_in[6];
    const float* be1 = (const float*)d_in[7];
    const float* W2 = (const float*)d_in[8];
    const float* b2 = (const float*)d_in[9];
    const float* ga2 = (const float*)d_in[10];
    const float* be2 = (const float*)d_in[11];
    const float* W3 = (const float*)d_in[12];
    const float* b3 = (const float*)d_in[13];

    const int N = in_sizes[0] / 128;
    const int E = in_sizes[1];
    float* outp = (float*)d_out;

    void *p_deg, *p_dinv, *p_ns, *p_norm, *p_h2, *p_out, *p_h;
    cudaGetSymbolAddress(&p_deg, g_deg);
    cudaGetSymbolAddress(&p_dinv, g_dinv);
    cudaGetSymbolAddress(&p_ns, g_normself);
    cudaGetSymbolAddress(&p_norm, g_norm);
    cudaGetSymbolAddress(&p_h2, g_h2);
    cudaGetSymbolAddress(&p_out, g_out);
    cudaGetSymbolAddress(&p_h, g_h);
    float* deg = (float*)p_deg;
    float* dinv = (float*)p_dinv;
    float* normself = (float*)p_ns;
    float* norm = (float*)p_norm;
    float* h2 = (float*)p_h2;
    float* agg = (float*)p_out;
    float* act = (float*)p_h;

    const float invN = 1.0f / (float)N;

    // --- normalization precompute ---
    k_deg_init<<<cdiv(N, 256), 256>>>(deg, N);
    k_deg_acc<<<cdiv(E, 256), 256>>>(dst, weight, deg, E);
    k_dinv<<<cdiv(N, 256), 256>>>(deg, dinv, normself, N);
    k_norm<<<cdiv(E, 256), 256>>>(src, dst, weight, dinv, norm, E);

    // ---------------- Layer 1: 128 -> 128 ----------------
    {
        constexpr int F = 128;
        const int count4 = N * (F / 4);
        k_gemm<128, 128><<<cdiv(N, 64), 256>>>(x, W1, h2, N);
        k_init_out<F><<<cdiv(count4, 256), 256>>>((const float4*)h2, b1, normself,
                                                  (float4*)agg, count4);
        {
            constexpr int EPW = 32 / (F / 4);  // 1
            int warps = cdiv(E, EPW);
            k_scatter<F><<<cdiv(warps, 8), 256>>>(src, dst, norm, h2, agg, E);
        }
        k_zero_stats<<<1, 256>>>();
        k_bn_stats<F><<<400, 256>>>(agg, N);
        k_bn_finalize<F><<<1, 128>>>(ga1, be1, invN);
        k_bn_apply<F><<<cdiv(count4, 256), 256>>>((const float4*)agg, (float4*)act, count4);
    }

    // ---------------- Layer 2: 128 -> 64 ----------------
    {
        constexpr int F = 64;
        const int count4 = N * (F / 4);
        k_gemm<128, 64><<<cdiv(N, 64), 256>>>(act, W2, h2, N);
        k_init_out<F><<<cdiv(count4, 256), 256>>>((const float4*)h2, b2, normself,
                                                  (float4*)agg, count4);
        {
            constexpr int EPW = 32 / (F / 4);  // 2
            int warps = cdiv(E, EPW);
            k_scatter<F><<<cdiv(warps, 8), 256>>>(src, dst, norm, h2, agg, E);
        }
        k_zero_stats<<<1, 256>>>();
        k_bn_stats<F><<<400, 256>>>(agg, N);
        k_bn_finalize<F><<<1, 128>>>(ga2, be2, invN);
        k_bn_apply<F><<<cdiv(count4, 256), 256>>>((const float4*)agg, (float4*)act, count4);
    }

    // ---------------- Layer 3: 64 -> 32 (writes d_out) ----------------
    {
        constexpr int F = 32;
        const int count4 = N * (F / 4);
        k_gemm<64, 32><<<cdiv(N, 64), 256>>>(act, W3, h2, N);
        k_init_out<F><<<cdiv(count4, 256), 256>>>((const float4*)h2, b3, normself,
                                                  (float4*)outp, count4);
        {
            constexpr int EPW = 32 / (F / 4);  // 4
            int warps = cdiv(E, EPW);
            k_scatter<F><<<cdiv(warps, 8), 256>>>(src, dst, norm, h2, outp, E);
        }
    }
}

// round 2
// speedup vs baseline: 1.1313x; 1.1313x over previous
#include <cuda_runtime.h>
#include <cuda_bf16.h>
#include <cstdint>

#define EPS 1e-5f

static constexpr int MAX_N = 50048;    // nodes (actual 50000)
static constexpr int MAX_E = 600064;   // edges (actual 600000)

// ---------------- scratch (device globals; no allocation allowed) ------------
__device__ float  g_deg[MAX_N];
__device__ float  g_dinv[MAX_N];
__device__ float  g_normself[MAX_N];
__device__ float  g_norm[MAX_E];
__device__ float4 g_h2[MAX_N * 32];    // up to 128 floats/node (GEMM output)
__device__ float4 g_out[MAX_N * 32];   // aggregation output
__device__ float  g_stats[256];        // [0..128) sum, [128..256) sumsq
__device__ __align__(16) float g_scale[128];
__device__ __align__(16) float g_shift[128];

// ---------------- small prep kernels ----------------------------------------
__global__ void k_deg_init(float* deg, int n) {
    int i = blockIdx.x * blockDim.x + threadIdx.x;
    if (i < n) deg[i] = 1.0f;   // self loop weight
}

__global__ void k_deg_acc(const int* __restrict__ dst, const float* __restrict__ w,
                          float* deg, int e) {
    int i = blockIdx.x * blockDim.x + threadIdx.x;
    if (i < e) atomicAdd(deg + dst[i], w[i]);
}

__global__ void k_dinv(const float* __restrict__ deg, float* dinv, float* normself, int n) {
    int i = blockIdx.x * blockDim.x + threadIdx.x;
    if (i < n) {
        float d = deg[i];
        float r = (d > 0.0f) ? rsqrtf(d) : 0.0f;
        dinv[i] = r;
        normself[i] = r * r;
    }
}

// 4 edges per thread for MLP
__global__ void k_norm(const int* __restrict__ src, const int* __restrict__ dst,
                       const float* __restrict__ w, const float* __restrict__ dinv,
                       float* norm, int e) {
    int i0 = (blockIdx.x * blockDim.x + threadIdx.x) * 4;
    if (i0 + 3 < e) {
        int4 s4 = *reinterpret_cast<const int4*>(src + i0);
        int4 d4 = *reinterpret_cast<const int4*>(dst + i0);
        float4 w4 = *reinterpret_cast<const float4*>(w + i0);
        float a0 = dinv[s4.x], a1 = dinv[s4.y], a2 = dinv[s4.z], a3 = dinv[s4.w];
        float c0 = dinv[d4.x], c1 = dinv[d4.y], c2 = dinv[d4.z], c3 = dinv[d4.w];
        float4 r = make_float4(a0 * w4.x * c0, a1 * w4.y * c1, a2 * w4.z * c2, a3 * w4.w * c3);
        *reinterpret_cast<float4*>(norm + i0) = r;
    } else {
        for (int i = i0; i < e; i++) norm[i] = dinv[src[i]] * w[i] * dinv[dst[i]];
    }
}

__global__ void k_zero_stats() {
    int i = threadIdx.x;
    if (i < 256) g_stats[i] = 0.0f;
}

// ---------------- tf32 helpers ------------------------------------------------
__device__ __forceinline__ uint32_t f2tf32(float f) {
    uint32_t r;
    asm("cvt.rna.tf32.f32 %0, %1;" : "=r"(r) : "f"(f));
    return r;
}

__device__ __forceinline__ void mma_tf32(float c[4], uint32_t a0, uint32_t a1,
                                         uint32_t a2, uint32_t a3,
                                         uint32_t b0, uint32_t b1) {
    asm volatile(
        "mma.sync.aligned.m16n8k8.row.col.f32.tf32.tf32.f32 "
        "{%0,%1,%2,%3}, {%4,%5,%6,%7}, {%8,%9}, {%0,%1,%2,%3};"
        : "+f"(c[0]), "+f"(c[1]), "+f"(c[2]), "+f"(c[3])
        : "r"(a0), "r"(a1), "r"(a2), "r"(a3), "r"(b0), "r"(b1));
}

// ---------------- tf32 tensor-core GEMM: C[M,NOUT] = A[M,K] @ B[K,NOUT] -------
// Optional fused BatchNorm(scale/shift from g_scale/g_shift) + ReLU on A load.
// Block: 256 threads (8 warps), BM=128 rows; whole K staged in smem.
template <int K, int NOUT, bool BN>
__global__ void k_gemm_tc(const float* __restrict__ A, const float* __restrict__ B,
                          float* __restrict__ C, int M) {
    constexpr int BM = 128;
    constexpr int SA = K + 4;       // A smem row stride (floats) - conflict free
    constexpr int SB = NOUT + 8;    // B smem row stride (floats) - conflict free
    constexpr int NT = NOUT / 8;    // n-tiles per warp

    extern __shared__ uint32_t sm[];
    uint32_t* As = sm;              // [BM][SA]
    uint32_t* Bs = sm + BM * SA;    // [K][SB]

    const int tid = threadIdx.x;
    const int lane = tid & 31;
    const int warp = tid >> 5;
    const int rowBase = blockIdx.x * BM;

    // --- stage B (K x NOUT) with tf32 conversion ---
    for (int l = tid; l < K * NOUT / 4; l += 256) {
        int r = l / (NOUT / 4);
        int c4 = l % (NOUT / 4);
        float4 v = *reinterpret_cast<const float4*>(B + (size_t)r * NOUT + c4 * 4);
        uint32_t* p = Bs + r * SB + c4 * 4;
        p[0] = f2tf32(v.x); p[1] = f2tf32(v.y); p[2] = f2tf32(v.z); p[3] = f2tf32(v.w);
    }
    // --- stage A (BM x K) with optional BN+ReLU, tf32 conversion ---
    for (int l = tid; l < BM * K / 4; l += 256) {
        int r = l / (K / 4);
        int c4 = l % (K / 4);
        int gr = rowBase + r;
        float4 v = make_float4(0.f, 0.f, 0.f, 0.f);
        if (gr < M) v = *reinterpret_cast<const float4*>(A + (size_t)gr * K + c4 * 4);
        if (BN) {
            float4 sc = *reinterpret_cast<const float4*>(g_scale + c4 * 4);
            float4 sh = *reinterpret_cast<const float4*>(g_shift + c4 * 4);
            v.x = fmaxf(fmaf(v.x, sc.x, sh.x), 0.f);
            v.y = fmaxf(fmaf(v.y, sc.y, sh.y), 0.f);
            v.z = fmaxf(fmaf(v.z, sc.z, sh.z), 0.f);
            v.w = fmaxf(fmaf(v.w, sc.w, sh.w), 0.f);
        }
        uint32_t* p = As + r * SA + c4 * 4;
        p[0] = f2tf32(v.x); p[1] = f2tf32(v.y); p[2] = f2tf32(v.z); p[3] = f2tf32(v.w);
    }
    __syncthreads();

    // --- compute: warp handles rows [warp*16, warp*16+16) ---
    float acc[NT][4];
#pragma unroll
    for (int nt = 0; nt < NT; nt++) {
        acc[nt][0] = 0.f; acc[nt][1] = 0.f; acc[nt][2] = 0.f; acc[nt][3] = 0.f;
    }

    const int r0 = (warp << 4) + (lane >> 2);   // row of a0/a2 within tile
    const int c0 = lane & 3;                    // k sub-index
    const int bcol = lane >> 2;                 // B fragment column

#pragma unroll 4
    for (int kk = 0; kk < K; kk += 8) {
        uint32_t a0 = As[r0 * SA + kk + c0];
        uint32_t a1 = As[(r0 + 8) * SA + kk + c0];
        uint32_t a2 = As[r0 * SA + kk + c0 + 4];
        uint32_t a3 = As[(r0 + 8) * SA + kk + c0 + 4];
#pragma unroll
        for (int nt = 0; nt < NT; nt++) {
            uint32_t b0 = Bs[(kk + c0) * SB + nt * 8 + bcol];
            uint32_t b1 = Bs[(kk + c0 + 4) * SB + nt * 8 + bcol];
            mma_tf32(acc[nt], a0, a1, a2, a3, b0, b1);
        }
    }

    // --- epilogue: c0,c1 -> row r0; c2,c3 -> row r0+8; cols nt*8 + (lane&3)*2 ---
    int gr0 = rowBase + r0;
    int gr1 = gr0 + 8;
    if (gr0 < M) {
#pragma unroll
        for (int nt = 0; nt < NT; nt++) {
            *reinterpret_cast<float2*>(C + (size_t)gr0 * NOUT + nt * 8 + c0 * 2) =
                make_float2(acc[nt][0], acc[nt][1]);
        }
    }
    if (gr1 < M) {
#pragma unroll
        for (int nt = 0; nt < NT; nt++) {
            *reinterpret_cast<float2*>(C + (size_t)gr1 * NOUT + nt * 8 + c0 * 2) =
                make_float2(acc[nt][2], acc[nt][3]);
        }
    }
}

// ---------------- out = normself * h2 + bias (self-loop + bias) -------------
template <int FEAT>
__global__ void k_init_out(const float4* __restrict__ h2, const float* __restrict__ b,
                           const float* __restrict__ normself, float4* __restrict__ out,
                           int count4) {
    constexpr int F4 = FEAT / 4;
    int idx = blockIdx.x * blockDim.x + threadIdx.x;
    if (idx >= count4) return;
    int node = idx / F4;
    int f4 = idx % F4;
    float ns = normself[node];
    float4 v = h2[idx];
    float4 bb = *reinterpret_cast<const float4*>(b + f4 * 4);
    out[idx] = make_float4(fmaf(ns, v.x, bb.x), fmaf(ns, v.y, bb.y),
                           fmaf(ns, v.z, bb.z), fmaf(ns, v.w, bb.w));
}

// ---------------- edge scatter with vectorized reductions -------------------
template <int FEAT>
__global__ void k_scatter(const int* __restrict__ src, const int* __restrict__ dst,
                          const float* __restrict__ norm, const float* __restrict__ h2,
                          float* __restrict__ out, int E) {
    constexpr int LPE = FEAT / 4;      // lanes per edge
    constexpr int EPW = 32 / LPE;      // edges per warp
    int lane = threadIdx.x & 31;
    int warpGlobal = (blockIdx.x * blockDim.x + threadIdx.x) >> 5;
    int sub = lane / LPE;
    int fc = lane % LPE;
    int e = warpGlobal * EPW + sub;
    if (e >= E) return;
    int s = src[e];
    int d = dst[e];
    float n = norm[e];
    float4 v = *reinterpret_cast<const float4*>(h2 + (size_t)s * FEAT + fc * 4);
    float mx = v.x * n, my = v.y * n, mz = v.z * n, mw = v.w * n;
    float* p = out + (size_t)d * FEAT + fc * 4;
    asm volatile("red.global.add.v4.f32 [%0], {%1, %2, %3, %4};"
                 :: "l"(p), "f"(mx), "f"(my), "f"(mz), "f"(mw)
                 : "memory");
}

// ---------------- BatchNorm: stats, finalize ---------------------------------
template <int FEAT>
__global__ void k_bn_stats(const float* __restrict__ h, int Nn) {
    constexpr int C = FEAT / 32;
    int lane = threadIdx.x & 31;
    int wid = threadIdx.x >> 5;
    int warpGlobal = (blockIdx.x * blockDim.x + threadIdx.x) >> 5;
    int nWarps = (gridDim.x * blockDim.x) >> 5;
    float s[C], q[C];
#pragma unroll
    for (int c = 0; c < C; c++) { s[c] = 0.f; q[c] = 0.f; }
    for (int r = warpGlobal; r < Nn; r += nWarps) {
        const float* p = h + (size_t)r * FEAT;
#pragma unroll
        for (int c = 0; c < C; c++) {
            float v = p[c * 32 + lane];
            s[c] += v;
            q[c] += v * v;
        }
    }
    __shared__ float sh_s[8][FEAT];
    __shared__ float sh_q[8][FEAT];
#pragma unroll
    for (int c = 0; c < C; c++) {
        sh_s[wid][c * 32 + lane] = s[c];
        sh_q[wid][c * 32 + lane] = q[c];
    }
    __syncthreads();
    int tid = threadIdx.x;
    if (tid < FEAT) {
        float a = 0.f, b = 0.f;
#pragma unroll
        for (int w = 0; w < 8; w++) { a += sh_s[w][tid]; b += sh_q[w][tid]; }
        atomicAdd(&g_stats[tid], a);
        atomicAdd(&g_stats[128 + tid], b);
    }
}

template <int FEAT>
__global__ void k_bn_finalize(const float* __restrict__ gamma, const float* __restrict__ beta,
                              float invN) {
    int f = threadIdx.x;
    if (f < FEAT) {
        float s = g_stats[f];
        float q = g_stats[128 + f];
        float mean = s * invN;
        float var = q * invN - mean * mean;
        float sc = gamma[f] * rsqrtf(var + EPS);
        g_scale[f] = sc;
        g_shift[f] = beta[f] - mean * sc;
    }
}

// ---------------- host orchestration -----------------------------------------
static inline int cdiv(int a, int b) { return (a + b - 1) / b; }

extern "C" void kernel_launch(void* const* d_in, const int* in_sizes, int n_in,
                              void* d_out, int out_size) {
    const float* x      = (const float*)d_in[0];
    const int*   src    = (const int*)d_in[1];
    const int*   dst    = (const int*)d_in[2];
    const float* weight = (const float*)d_in[3];
    const float* W1 = (const float*)d_in[4];
    const float* b1 = (const float*)d_in[5];
    const float* ga1 = (const float*)d_in[6];
    const float* be1 = (const float*)d_in[7];
    const float* W2 = (const float*)d_in[8];
    const float* b2 = (const float*)d_in[9];
    const float* ga2 = (const float*)d_in[10];
    const float* be2 = (const float*)d_in[11];
    const float* W3 = (const float*)d_in[12];
    const float* b3 = (const float*)d_in[13];

    const int N = in_sizes[0] / 128;
    const int E = in_sizes[1];
    float* outp = (float*)d_out;

    void *p_deg, *p_dinv, *p_ns, *p_norm, *p_h2, *p_out;
    cudaGetSymbolAddress(&p_deg, g_deg);
    cudaGetSymbolAddress(&p_dinv, g_dinv);
    cudaGetSymbolAddress(&p_ns, g_normself);
    cudaGetSymbolAddress(&p_norm, g_norm);
    cudaGetSymbolAddress(&p_h2, g_h2);
    cudaGetSymbolAddress(&p_out, g_out);
    float* deg = (float*)p_deg;
    float* dinv = (float*)p_dinv;
    float* normself = (float*)p_ns;
    float* norm = (float*)p_norm;
    float* h2 = (float*)p_h2;
    float* agg = (float*)p_out;

    const float invN = 1.0f / (float)N;

    // smem sizes per GEMM instantiation
    const int smem1 = (128 * (128 + 4) + 128 * (128 + 8)) * 4;   // 137216
    const int smem2 = (128 * (128 + 4) + 128 * (64 + 8)) * 4;    // 104448
    const int smem3 = (128 * (64 + 4) + 64 * (32 + 8)) * 4;      // 45056
    cudaFuncSetAttribute(k_gemm_tc<128, 128, false>,
                         cudaFuncAttributeMaxDynamicSharedMemorySize, smem1);
    cudaFuncSetAttribute(k_gemm_tc<128, 64, true>,
                         cudaFuncAttributeMaxDynamicSharedMemorySize, smem2);
    cudaFuncSetAttribute(k_gemm_tc<64, 32, true>,
                         cudaFuncAttributeMaxDynamicSharedMemorySize, smem3);

    // --- normalization precompute ---
    k_deg_init<<<cdiv(N, 256), 256>>>(deg, N);
    k_deg_acc<<<cdiv(E, 256), 256>>>(dst, weight, deg, E);
    k_dinv<<<cdiv(N, 256), 256>>>(deg, dinv, normself, N);
    k_norm<<<cdiv(E, 1024), 256>>>(src, dst, weight, dinv, norm, E);

    const int gemmGrid = cdiv(N, 128);

    // ---------------- Layer 1: 128 -> 128 ----------------
    {
        constexpr int F = 128;
        const int count4 = N * (F / 4);
        k_gemm_tc<128, 128, false><<<gemmGrid, 256, smem1>>>(x, W1, h2, N);
        k_init_out<F><<<cdiv(count4, 256), 256>>>((const float4*)h2, b1, normself,
                                                  (float4*)agg, count4);
        {
            constexpr int EPW = 32 / (F / 4);  // 1
            int warps = cdiv(E, EPW);
            k_scatter<F><<<cdiv(warps, 8), 256>>>(src, dst, norm, h2, agg, E);
        }
        k_zero_stats<<<1, 256>>>();
        k_bn_stats<F><<<400, 256>>>(agg, N);
        k_bn_finalize<F><<<1, 128>>>(ga1, be1, invN);
    }

    // ---------------- Layer 2: 128 -> 64 (BN+ReLU fused into A load) -------
    {
        constexpr int F = 64;
        const int count4 = N * (F / 4);
        k_gemm_tc<128, 64, true><<<gemmGrid, 256, smem2>>>(agg, W2, h2, N);
        k_init_out<F><<<cdiv(count4, 256), 256>>>((const float4*)h2, b2, normself,
                                                  (float4*)agg, count4);
        {
            constexpr int EPW = 32 / (F / 4);  // 2
            int warps = cdiv(E, EPW);
            k_scatter<F><<<cdiv(warps, 8), 256>>>(src, dst, norm, h2, agg, E);
        }
        k_zero_stats<<<1, 256>>>();
        k_bn_stats<F><<<400, 256>>>(agg, N);
        k_bn_finalize<F><<<1, 64>>>(ga2, be2, invN);
    }

    // ---------------- Layer 3: 64 -> 32 (writes d_out) ----------------
    {
        constexpr int F = 32;
        const int count4 = N * (F / 4);
        k_gemm_tc<64, 32, true><<<gemmGrid, 256, smem3>>>(agg, W3, h2, N);
        k_init_out<F><<<cdiv(count4, 256), 256>>>((const float4*)h2, b3, normself,
                                                  (float4*)outp, count4);
        {
            constexpr int EPW = 32 / (F / 4);  // 4
            int warps = cdiv(E, EPW);
            k_scatter<F><<<cdiv(warps, 8), 256>>>(src, dst, norm, h2, outp, E);
        }
    }
}